// round 11
// baseline (speedup 1.0000x reference)
#include <cuda_runtime.h>

// HBV hydrological model scan, sm_103a.
// One thread per (basin, nmul) cell: tid = b*NMUL + m.
// 365 sequential steps; all state in registers; outputs:
//   d_out[0 .. T*B)            = Qsim_avg (mean over nmul)
//   d_out[T*B .. T*B + T*B*4)  = Qsim
//
// Input order (setup_inputs dict insertion order):
//   0: forcing (T,B,3)  [prcp, tmean, pet]
//   1: parBETA  2: parFC   3: parK0   4: parK1   5: parK2
//   6: parLP    7: parPERC 8: parUZL  9: parTT  10: parCFMAX
//  11: parCFR  12: parCWH 13: parBETAET 14: parC        (all (B,4))

#define T_STEPS 365
#define BATCH   20000
#define NMUL    4
#define NCELLS  (BATCH * NMUL)

__global__ __launch_bounds__(256, 4)
void hbv_scan_kernel(const float* __restrict__ forcing,
                     const float* __restrict__ pBETA,
                     const float* __restrict__ pFC,
                     const float* __restrict__ pK0,
                     const float* __restrict__ pK1,
                     const float* __restrict__ pK2,
                     const float* __restrict__ pLP,
                     const float* __restrict__ pPERC,
                     const float* __restrict__ pUZL,
                     const float* __restrict__ pTT,
                     const float* __restrict__ pCFMAX,
                     const float* __restrict__ pCFR,
                     const float* __restrict__ pCWH,
                     const float* __restrict__ pBETAET,
                     const float* __restrict__ pC,
                     float* __restrict__ qavg,   // (T, B)
                     float* __restrict__ qsim)   // (T, B, NMUL)
{
    const int tid = blockIdx.x * blockDim.x + threadIdx.x;
    if (tid >= NCELLS) return;           // NCELLS is a multiple of 32 -> whole warps drop out
    const int b = tid >> 2;              // basin index
    const int m = tid & 3;               // nmul index

    // Per-cell parameters (coalesced: (B, NMUL) row-major == tid-linear)
    const float BETA   = pBETA[tid];
    const float FC     = pFC[tid];
    const float K0     = pK0[tid];
    const float K1     = pK1[tid];
    const float K2     = pK2[tid];
    const float LP     = pLP[tid];
    const float PERC   = pPERC[tid];
    const float UZL    = pUZL[tid];
    const float TT     = pTT[tid];
    const float CFMAX  = pCFMAX[tid];
    const float CFR    = pCFR[tid];
    const float CWH    = pCWH[tid];
    const float BETAET = pBETAET[tid];
    const float C      = pC[tid];

    // Hoisted invariants
    const float invFC   = 1.0f / FC;
    const float invLPFC = 1.0f / (LP * FC);
    const float cfr_cf  = CFR * CFMAX;
    const float eps     = 1e-6f;

    // State
    float snow = eps, melt = 0.0f, sm = 0.0f, suz = 0.0f, slz = 0.0f;

    const float* __restrict__ frc = forcing + (size_t)b * 3;

    for (int t = 0; t < T_STEPS; ++t) {
        const float* f = frc + (size_t)t * (BATCH * 3);
        const float p   = f[0];
        const float tv  = f[1];
        const float pet = f[2];

        // --- snow routine ---
        const float td      = tv - TT;
        const bool  is_rain = td > 0.0f;
        const float rain       = is_rain ? p : 0.0f;
        const float snow_input = is_rain ? 0.0f : p;

        float snow1       = snow + snow_input;
        const float pot_melt    = CFMAX * fmaxf(td, 0.0f);
        const float melt_amount = fminf(pot_melt, snow1);
        snow1 -= melt_amount;
        float melt1 = melt + melt_amount;

        const float pot_refreeze = cfr_cf * fmaxf(-td, 0.0f);
        const float refreeze     = fminf(pot_refreeze, melt1);
        snow  = snow1 + refreeze;
        melt1 -= refreeze;

        const float tosoil = fmaxf(melt1 - CWH * snow, 0.0f);
        melt = melt1 - tosoil;

        // --- soil routine ---
        const float soil_wet = fminf(__powf(fmaxf(sm * invFC, eps), BETA), 1.0f);
        const float recharge = (rain + tosoil) * soil_wet;
        float sm1 = sm + rain + tosoil - recharge;
        const float excess = fmaxf(sm1 - FC, 0.0f);
        sm1 -= excess;

        const float ef1        = fminf(fmaxf(sm1 * invLPFC, 0.0f), 1.0f);
        const float evapfactor = fminf(__powf(fmaxf(ef1, eps), BETAET), 1.0f);
        const float etact      = fminf(pet * evapfactor, sm1);
        const float sm_ae      = fmaxf(sm1 - etact, eps);

        const float sm_ratio  = fminf(sm_ae * invFC, 1.0f);
        const float capillary = fminf(slz, C * slz * (1.0f - sm_ratio));
        sm = fmaxf(sm_ae + capillary, eps);
        const float slz_ac = fmaxf(slz - capillary, eps);

        // --- response routine ---
        float suz1 = suz + recharge + excess;
        const float perc_flux = fminf(suz1, PERC);
        suz1 -= perc_flux;
        float slz1 = slz_ac + perc_flux;

        const float q0 = K0 * fmaxf(suz1 - UZL, 0.0f);
        suz1 -= q0;
        const float q1 = K1 * suz1;
        suz = suz1 - q1;
        const float q2 = K2 * slz1;
        slz = slz1 - q2;

        const float q = q0 + q1 + q2;

        // quad mean across nmul (lanes tid..tid+3 form a quad since warps are quad-aligned)
        float s = q + __shfl_xor_sync(0xffffffffu, q, 1);
        s      +=     __shfl_xor_sync(0xffffffffu, s, 2);

        qsim[(size_t)t * NCELLS + tid] = q;
        if (m == 0)
            qavg[(size_t)t * BATCH + b] = s * 0.25f;
    }
}

extern "C" void kernel_launch(void* const* d_in, const int* in_sizes, int n_in,
                              void* d_out, int out_size)
{
    const float* forcing = (const float*)d_in[0];
    const float* pBETA   = (const float*)d_in[1];
    const float* pFC     = (const float*)d_in[2];
    const float* pK0     = (const float*)d_in[3];
    const float* pK1     = (const float*)d_in[4];
    const float* pK2     = (const float*)d_in[5];
    const float* pLP     = (const float*)d_in[6];
    const float* pPERC   = (const float*)d_in[7];
    const float* pUZL    = (const float*)d_in[8];
    const float* pTT     = (const float*)d_in[9];
    const float* pCFMAX  = (const float*)d_in[10];
    const float* pCFR    = (const float*)d_in[11];
    const float* pCWH    = (const float*)d_in[12];
    const float* pBETAET = (const float*)d_in[13];
    const float* pC      = (const float*)d_in[14];

    float* qavg = (float*)d_out;                           // (T, B)
    float* qsim = (float*)d_out + (size_t)T_STEPS * BATCH; // (T, B, NMUL)

    const int threads = 256;
    const int blocks  = (NCELLS + threads - 1) / threads;
    hbv_scan_kernel<<<blocks, threads>>>(forcing,
        pBETA, pFC, pK0, pK1, pK2, pLP, pPERC, pUZL, pTT,
        pCFMAX, pCFR, pCWH, pBETAET, pC,
        qavg, qsim);
}